// round 15
// baseline (speedup 1.0000x reference)
#include <cuda_runtime.h>
#include <math.h>

#define BB      8
#define LSEQ    4096
#define DIMC    384
#define NDEPTH  6
#define NSTATE  16
#define NCONV   4
#define DINNER  768
#define DTRANK  24
#define HIDF    768
#define MTOK    (BB*LSEQ)             // 32768
#define DBLW    (DTRANK + 2*NSTATE)   // 56

// ---------------- scratch (static device globals; no allocation) ----------------
__device__ float g_x  [MTOK*DIMC];
__device__ float g_xn [MTOK*DIMC];
__device__ float g_xz [MTOK*2*DINNER];
__device__ float g_xi [MTOK*DINNER];
__device__ float g_dbl[MTOK*DBLW];
__device__ float g_dt [MTOK*DINNER];
__device__ float g_y  [MTOK*DINNER];

// ---------------- helpers ----------------
__device__ __forceinline__ float siluf(float v) {
    return v / (1.0f + expf(-v));
}
__device__ __forceinline__ float softplusf(float v) {
    return (v >= 0.0f) ? (v + log1pf(expf(-v))) : log1pf(expf(v));
}
__device__ __forceinline__ float geluf(float v) {
    float c = 0.7978845608028654f * (v + 0.044715f * v * v * v);
    return 0.5f * v * (1.0f + tanhf(c));
}

// ---------------- elementwise: x = x + pos_emb ----------------
__global__ void add_pos_kernel(const float* __restrict__ x,
                               const float* __restrict__ pos,
                               float* __restrict__ out) {
    int idx = blockIdx.x * blockDim.x + threadIdx.x;
    if (idx >= MTOK * DIMC / 4) return;
    int m  = idx / (DIMC / 4);
    int c4 = idx % (DIMC / 4);
    int l  = m & (LSEQ - 1);
    float4 xv = ((const float4*)x)[idx];
    float4 pv = ((const float4*)pos)[l * (DIMC / 4) + c4];
    xv.x += pv.x; xv.y += pv.y; xv.z += pv.z; xv.w += pv.w;
    ((float4*)out)[idx] = xv;
}

// ---------------- layernorm over DIMC=384 (one warp per token) ----------------
__global__ void ln_kernel(const float* __restrict__ x, float* __restrict__ o,
                          const float* __restrict__ s, const float* __restrict__ bb) {
    int gwarp = (blockIdx.x * blockDim.x + threadIdx.x) >> 5;
    int lane  = threadIdx.x & 31;
    if (gwarp >= MTOK) return;
    const float* xp = x + (size_t)gwarp * DIMC;
    float4 v0 = *(const float4*)(xp + lane * 4);
    float4 v1 = *(const float4*)(xp + 128 + lane * 4);
    float4 v2 = *(const float4*)(xp + 256 + lane * 4);
    float sum = v0.x + v0.y + v0.z + v0.w
              + v1.x + v1.y + v1.z + v1.w
              + v2.x + v2.y + v2.z + v2.w;
    #pragma unroll
    for (int off = 16; off >= 1; off >>= 1) sum += __shfl_xor_sync(0xffffffffu, sum, off);
    float mean = sum * (1.0f / DIMC);
    float q = 0.0f;
    #define QACC(t) { float d_ = (t) - mean; q = fmaf(d_, d_, q); }
    QACC(v0.x) QACC(v0.y) QACC(v0.z) QACC(v0.w)
    QACC(v1.x) QACC(v1.y) QACC(v1.z) QACC(v1.w)
    QACC(v2.x) QACC(v2.y) QACC(v2.z) QACC(v2.w)
    #undef QACC
    #pragma unroll
    for (int off = 16; off >= 1; off >>= 1) q += __shfl_xor_sync(0xffffffffu, q, off);
    float rstd = rsqrtf(q * (1.0f / DIMC) + 1e-5f);

    float4 s0 = *(const float4*)(s + lane * 4);
    float4 s1 = *(const float4*)(s + 128 + lane * 4);
    float4 s2 = *(const float4*)(s + 256 + lane * 4);
    float4 b0 = *(const float4*)(bb + lane * 4);
    float4 b1 = *(const float4*)(bb + 128 + lane * 4);
    float4 b2 = *(const float4*)(bb + 256 + lane * 4);
    float* op = o + (size_t)gwarp * DIMC;
    float4 r;
    r.x = (v0.x - mean) * rstd * s0.x + b0.x;
    r.y = (v0.y - mean) * rstd * s0.y + b0.y;
    r.z = (v0.z - mean) * rstd * s0.z + b0.z;
    r.w = (v0.w - mean) * rstd * s0.w + b0.w;
    *(float4*)(op + lane * 4) = r;
    r.x = (v1.x - mean) * rstd * s1.x + b1.x;
    r.y = (v1.y - mean) * rstd * s1.y + b1.y;
    r.z = (v1.z - mean) * rstd * s1.z + b1.z;
    r.w = (v1.w - mean) * rstd * s1.w + b1.w;
    *(float4*)(op + 128 + lane * 4) = r;
    r.x = (v2.x - mean) * rstd * s2.x + b2.x;
    r.y = (v2.y - mean) * rstd * s2.y + b2.y;
    r.z = (v2.z - mean) * rstd * s2.z + b2.z;
    r.w = (v2.w - mean) * rstd * s2.w + b2.w;
    *(float4*)(op + 256 + lane * 4) = r;
}

// ---------------- proven TN SGEMM (round-5 config): C[M,N] = A[M,K] @ W[N,K]^T ----
// EPI: 0=store, 1=softplus(v+bias), 2=gelu(v+bias), 3=C+=v, 4=C+=v+bias
#define BM 128
#define BN 128
#define BKK 8

template <int EPI>
__global__ void __launch_bounds__(256)
sgemm_tn(const float* __restrict__ A, const float* __restrict__ W,
         float* __restrict__ C, const float* __restrict__ bias,
         int M, int N, int K, int lda, int ldw, int ldc) {
    __shared__ float As[BKK][BM + 4];
    __shared__ float Bs[BKK][BN + 4];

    int m0 = blockIdx.y * BM;
    int n0 = blockIdx.x * BN;
    int tid = threadIdx.x;
    int lrow = tid >> 1;            // 0..127
    int lcol = (tid & 1) * 4;       // 0 or 4
    int tx = tid & 15, ty = tid >> 4;

    float acc[8][8];
    #pragma unroll
    for (int i = 0; i < 8; i++)
        #pragma unroll
        for (int j = 0; j < 8; j++) acc[i][j] = 0.0f;

    // first prefetch
    float4 ra = *(const float4*)(A + (size_t)(m0 + lrow) * lda + lcol);
    float4 rb;
    {
        int n = n0 + lrow;
        rb = (n < N) ? *(const float4*)(W + (size_t)n * ldw + lcol)
                     : make_float4(0.f, 0.f, 0.f, 0.f);
    }

    for (int k0 = 0; k0 < K; k0 += BKK) {
        As[lcol + 0][lrow] = ra.x;
        As[lcol + 1][lrow] = ra.y;
        As[lcol + 2][lrow] = ra.z;
        As[lcol + 3][lrow] = ra.w;
        Bs[lcol + 0][lrow] = rb.x;
        Bs[lcol + 1][lrow] = rb.y;
        Bs[lcol + 2][lrow] = rb.z;
        Bs[lcol + 3][lrow] = rb.w;
        __syncthreads();

        if (k0 + BKK < K) {
            ra = *(const float4*)(A + (size_t)(m0 + lrow) * lda + (k0 + BKK) + lcol);
            int n = n0 + lrow;
            rb = (n < N) ? *(const float4*)(W + (size_t)n * ldw + (k0 + BKK) + lcol)
                         : make_float4(0.f, 0.f, 0.f, 0.f);
        }

        #pragma unroll
        for (int k = 0; k < BKK; k++) {
            float4 a0 = *(const float4*)&As[k][ty * 4];
            float4 a1 = *(const float4*)&As[k][ty * 4 + 64];
            float4 b0 = *(const float4*)&Bs[k][tx * 4];
            float4 b1 = *(const float4*)&Bs[k][tx * 4 + 64];
            float av[8] = {a0.x, a0.y, a0.z, a0.w, a1.x, a1.y, a1.z, a1.w};
            float bv[8] = {b0.x, b0.y, b0.z, b0.w, b1.x, b1.y, b1.z, b1.w};
            #pragma unroll
            for (int ii = 0; ii < 8; ii++)
                #pragma unroll
                for (int jj = 0; jj < 8; jj++)
                    acc[ii][jj] = fmaf(av[ii], bv[jj], acc[ii][jj]);
        }
        __syncthreads();
    }

    // epilogue
    #pragma unroll
    for (int ii = 0; ii < 8; ii++) {
        int r = m0 + ty * 4 + ((ii < 4) ? ii : 64 + ii - 4);
        float* crow = C + (size_t)r * ldc;
        #pragma unroll
        for (int jj = 0; jj < 8; jj++) {
            int c = n0 + tx * 4 + ((jj < 4) ? jj : 64 + jj - 4);
            if (c >= N) continue;
            float v = acc[ii][jj];
            if (EPI == 0) {
                crow[c] = v;
            } else if (EPI == 1) {
                crow[c] = softplusf(v + bias[c]);
            } else if (EPI == 2) {
                crow[c] = geluf(v + bias[c]);
            } else if (EPI == 3) {
                crow[c] += v;
            } else {
                crow[c] += v + bias[c];
            }
        }
    }
}

// ---------------- narrow xproj GEMM: C[M,56] = A[M,768] @ W[56,768]^T ----------
// Same single-buffer BKK=8 recipe, BN=64 tile, microtile 8x4.
__global__ void __launch_bounds__(256)
xgemm64_tn(const float* __restrict__ A, const float* __restrict__ W,
           float* __restrict__ C, int M, int K) {
    __shared__ float As[BKK][BM + 4];
    __shared__ float Bs[BKK][64 + 4];

    int m0 = blockIdx.y * BM;
    int tid = threadIdx.x;
    int lrow = tid >> 1;            // 0..127  (A staging)
    int lcol = (tid & 1) * 4;       // 0 or 4
    int tx = tid & 15, ty = tid >> 4;

    // B staging: threads 0..127 load 64 rows x 8 cols
    int brow = (tid & 127) >> 1;    // 0..63
    int bcol = (tid & 1) * 4;
    bool bload = (tid < 128);
    bool bvalid = bload && (brow < DBLW);

    float acc[8][4];
    #pragma unroll
    for (int i = 0; i < 8; i++)
        #pragma unroll
        for (int j = 0; j < 4; j++) acc[i][j] = 0.0f;

    const float* Ap = A + (size_t)(m0 + lrow) * K;
    const float* Wp = W + (size_t)(bvalid ? brow : 0) * K;

    float4 ra = *(const float4*)(Ap + lcol);
    float4 rb = bvalid ? *(const float4*)(Wp + bcol)
                       : make_float4(0.f, 0.f, 0.f, 0.f);

    for (int k0 = 0; k0 < K; k0 += BKK) {
        As[lcol + 0][lrow] = ra.x;
        As[lcol + 1][lrow] = ra.y;
        As[lcol + 2][lrow] = ra.z;
        As[lcol + 3][lrow] = ra.w;
        if (bload) {
            Bs[bcol + 0][brow] = rb.x;
            Bs[bcol + 1][brow] = rb.y;
            Bs[bcol + 2][brow] = rb.z;
            Bs[bcol + 3][brow] = rb.w;
        }
        __syncthreads();

        if (k0 + BKK < K) {
            ra = *(const float4*)(Ap + (k0 + BKK) + lcol);
            rb = bvalid ? *(const float4*)(Wp + (k0 + BKK) + bcol)
                        : make_float4(0.f, 0.f, 0.f, 0.f);
        }

        #pragma unroll
        for (int k = 0; k < BKK; k++) {
            float4 a0 = *(const float4*)&As[k][ty * 4];
            float4 a1 = *(const float4*)&As[k][ty * 4 + 64];
            float4 b0 = *(const float4*)&Bs[k][tx * 4];
            float av[8] = {a0.x, a0.y, a0.z, a0.w, a1.x, a1.y, a1.z, a1.w};
            float bv[4] = {b0.x, b0.y, b0.z, b0.w};
            #pragma unroll
            for (int ii = 0; ii < 8; ii++)
                #pragma unroll
                for (int jj = 0; jj < 4; jj++)
                    acc[ii][jj] = fmaf(av[ii], bv[jj], acc[ii][jj]);
        }
        __syncthreads();
    }

    #pragma unroll
    for (int ii = 0; ii < 8; ii++) {
        int r = m0 + ty * 4 + ((ii < 4) ? ii : 64 + ii - 4);
        float* crow = C + (size_t)r * DBLW;
        #pragma unroll
        for (int jj = 0; jj < 4; jj++) {
            int c = tx * 4 + jj;
            if (c < DBLW) crow[c] = acc[ii][jj];
        }
    }
}

// ---------------- causal depthwise conv (DCONV=4) + silu ----------------
// each thread: 4 consecutive tokens x 4 channels (register tap reuse)
__global__ void conv_silu_kernel(const float* __restrict__ xz, float* __restrict__ xi,
                                 const float* __restrict__ w, const float* __restrict__ cb) {
    const int nD4 = DINNER / 4;
    int idx = blockIdx.x * blockDim.x + threadIdx.x;
    if (idx >= (MTOK / 4) * nD4) return;
    int mg = idx / nD4;
    int d4 = (idx % nD4) * 4;
    int m0 = mg * 4;
    int l0 = m0 & (LSEQ - 1);

    float4 w0 = *(const float4*)(w + (d4 + 0) * NCONV);
    float4 w1 = *(const float4*)(w + (d4 + 1) * NCONV);
    float4 w2 = *(const float4*)(w + (d4 + 2) * NCONV);
    float4 w3 = *(const float4*)(w + (d4 + 3) * NCONV);
    float4 cbv = *(const float4*)(cb + d4);

    float4 v[7];
    const float* base = xz + (size_t)m0 * (2 * DINNER) + d4;
    #pragma unroll
    for (int j = 0; j < 7; j++) {
        int dl = l0 - 3 + j;
        v[j] = (dl >= 0) ? *(const float4*)(base + (size_t)(j - 3) * (2 * DINNER))
                         : make_float4(0.f, 0.f, 0.f, 0.f);
    }

    const float wk0[4] = {w0.x, w0.y, w0.z, w0.w};
    const float wk1[4] = {w1.x, w1.y, w1.z, w1.w};
    const float wk2[4] = {w2.x, w2.y, w2.z, w2.w};
    const float wk3[4] = {w3.x, w3.y, w3.z, w3.w};

    #pragma unroll
    for (int tt = 0; tt < 4; tt++) {
        float4 acc = cbv;
        #pragma unroll
        for (int k = 0; k < NCONV; k++) {
            float4 xv = v[tt + k];
            acc.x = fmaf(xv.x, wk0[k], acc.x);
            acc.y = fmaf(xv.y, wk1[k], acc.y);
            acc.z = fmaf(xv.z, wk2[k], acc.z);
            acc.w = fmaf(xv.w, wk3[k], acc.w);
        }
        acc.x = siluf(acc.x);
        acc.y = siluf(acc.y);
        acc.z = siluf(acc.z);
        acc.w = siluf(acc.w);
        *(float4*)(xi + (size_t)(m0 + tt) * DINNER + d4) = acc;
    }
}

// ---------------- selective scan (gating with silu(z) fused) ----------------
__global__ void __launch_bounds__(256)
scan_kernel(const float* __restrict__ xi, const float* __restrict__ dt,
            const float* __restrict__ dbl, const float* __restrict__ A_log,
            const float* __restrict__ Dp, const float* __restrict__ xz,
            float* __restrict__ y) {
    int b    = blockIdx.x;
    int dblk = blockIdx.y;
    int tid  = threadIdx.x;
    int dl   = tid >> 4;
    int s    = tid & 15;
    int d    = dblk * 16 + dl;

    float aL2 = -expf(A_log[d * NSTATE + s]) * 1.4426950408889634f;
    float Dd  = Dp[d];
    float h = 0.0f;

    const float* dt_p = dt + (size_t)b * LSEQ * DINNER + d;
    const float* u_p  = xi + (size_t)b * LSEQ * DINNER + d;
    const float* bc_p = dbl + (size_t)b * LSEQ * DBLW;
    const float* z_p  = xz + (size_t)b * LSEQ * (2 * DINNER) + DINNER + d;
    float*       y_p  = y  + (size_t)b * LSEQ * DINNER + d;

    #pragma unroll 4
    for (int t = 0; t < LSEQ; t++) {
        float dtv = dt_p[(size_t)t * DINNER];
        float uv  = u_p[(size_t)t * DINNER];
        float Bv  = bc_p[(size_t)t * DBLW + DTRANK + s];
        float Cv  = bc_p[(size_t)t * DBLW + DTRANK + NSTATE + s];
        float dA  = exp2f(dtv * aL2);
        h = fmaf(h, dA, (dtv * uv) * Bv);
        float p = h * Cv;
        p += __shfl_xor_sync(0xffffffffu, p, 8);
        p += __shfl_xor_sync(0xffffffffu, p, 4);
        p += __shfl_xor_sync(0xffffffffu, p, 2);
        p += __shfl_xor_sync(0xffffffffu, p, 1);
        if (s == 0) {
            float zv = z_p[(size_t)t * (2 * DINNER)];
            y_p[(size_t)t * DINNER] = fmaf(uv, Dd, p) * siluf(zv);
        }
    }
}

// ---------------- host launcher ----------------
static inline int cdiv(int a, int b) { return (a + b - 1) / b; }

extern "C" void kernel_launch(void* const* d_in, const int* in_sizes, int n_in,
                              void* d_out, int out_size) {
    const float* x_in     = (const float*)d_in[0];
    const float* pos      = (const float*)d_in[1];
    const float* ln1_s    = (const float*)d_in[2];
    const float* ln1_b    = (const float*)d_in[3];
    const float* in_w     = (const float*)d_in[4];
    const float* conv_w   = (const float*)d_in[5];
    const float* conv_b   = (const float*)d_in[6];
    const float* xproj_w  = (const float*)d_in[7];
    const float* dtproj_w = (const float*)d_in[8];
    const float* dtproj_b = (const float*)d_in[9];
    const float* A_log    = (const float*)d_in[10];
    const float* Dp       = (const float*)d_in[11];
    const float* out_w    = (const float*)d_in[12];
    const float* ff_ln_s  = (const float*)d_in[13];
    const float* ff_ln_b  = (const float*)d_in[14];
    const float* ff_w1    = (const float*)d_in[15];
    const float* ff_b1    = (const float*)d_in[16];
    const float* ff_w2    = (const float*)d_in[17];
    const float* ff_b2    = (const float*)d_in[18];
    const float* lno_s    = (const float*)d_in[19];
    const float* lno_b    = (const float*)d_in[20];

    float *bx, *bxn, *bxz, *bxi, *bdbl, *bdt, *by;
    cudaGetSymbolAddress((void**)&bx,   g_x);
    cudaGetSymbolAddress((void**)&bxn,  g_xn);
    cudaGetSymbolAddress((void**)&bxz,  g_xz);
    cudaGetSymbolAddress((void**)&bxi,  g_xi);
    cudaGetSymbolAddress((void**)&bdbl, g_dbl);
    cudaGetSymbolAddress((void**)&bdt,  g_dt);
    cudaGetSymbolAddress((void**)&by,   g_y);

    const int EW_BLK = 256;
    int ew_dim  = cdiv(MTOK * DIMC / 4, EW_BLK);
    int ew_conv = cdiv((MTOK / 4) * (DINNER / 4), EW_BLK);

    // x = x + pos_emb
    add_pos_kernel<<<ew_dim, EW_BLK>>>(x_in, pos, bx);

    for (int i = 0; i < NDEPTH; i++) {
        // ---- mamba block ----
        ln_kernel<<<MTOK / 8, 256>>>(bx, bxn, ln1_s + (size_t)i * DIMC, ln1_b + (size_t)i * DIMC);

        // xz = xn @ in_w^T  [M,1536]
        sgemm_tn<0><<<dim3((2 * DINNER) / BN, MTOK / BM), 256>>>(
            bxn, in_w + (size_t)i * 2 * DINNER * DIMC, bxz, nullptr,
            MTOK, 2 * DINNER, DIMC, DIMC, DIMC, 2 * DINNER);

        // xi = silu(conv1d(xz[:, :768]))
        conv_silu_kernel<<<ew_conv, EW_BLK>>>(
            bxz, bxi, conv_w + (size_t)i * DINNER * NCONV, conv_b + (size_t)i * DINNER);

        // dbl = xi @ xproj_w^T  [M,56]  (narrow BN=64 kernel)
        xgemm64_tn<<<dim3(1, MTOK / BM), 256>>>(
            bxi, xproj_w + (size_t)i * DBLW * DINNER, bdbl, MTOK, DINNER);

        // dt = softplus(dbl[:, :24] @ dtproj_w^T + dtproj_b)  [M,768]
        sgemm_tn<1><<<dim3(cdiv(DINNER, BN), MTOK / BM), 256>>>(
            bdbl, dtproj_w + (size_t)i * DINNER * DTRANK, bdt,
            dtproj_b + (size_t)i * DINNER,
            MTOK, DINNER, DTRANK, DBLW, DTRANK, DINNER);

        // selective scan + gate -> y
        scan_kernel<<<dim3(BB, DINNER / 16), 256>>>(
            bxi, bdt, bdbl, A_log + (size_t)i * DINNER * NSTATE,
            Dp + (size_t)i * DINNER, bxz, by);

        // x += y @ out_w^T
        sgemm_tn<3><<<dim3(DIMC / BN, MTOK / BM), 256>>>(
            by, out_w + (size_t)i * DIMC * DINNER, bx, nullptr,
            MTOK, DIMC, DINNER, DINNER, DINNER, DIMC);

        // ---- feed-forward block ----
        ln_kernel<<<MTOK / 8, 256>>>(bx, bxn, ff_ln_s + (size_t)i * DIMC, ff_ln_b + (size_t)i * DIMC);

        // h = gelu(xn @ ff_w1^T + b1)
        sgemm_tn<2><<<dim3(HIDF / BN, MTOK / BM), 256>>>(
            bxn, ff_w1 + (size_t)i * HIDF * DIMC, by, ff_b1 + (size_t)i * HIDF,
            MTOK, HIDF, DIMC, DIMC, DIMC, HIDF);

        // x += h @ ff_w2^T + b2
        sgemm_tn<4><<<dim3(DIMC / BN, MTOK / BM), 256>>>(
            by, ff_w2 + (size_t)i * DIMC * HIDF, bx, ff_b2 + (size_t)i * DIMC,
            MTOK, DIMC, HIDF, HIDF, HIDF, DIMC);
    }

    // final layernorm -> d_out
    ln_kernel<<<MTOK / 8, 256>>>(bx, (float*)d_out, lno_s, lno_b);
}

// round 16
// speedup vs baseline: 1.6342x; 1.6342x over previous
#include <cuda_runtime.h>
#include <math.h>

#define BB      8
#define LSEQ    4096
#define DIMC    384
#define NDEPTH  6
#define NSTATE  16
#define NCONV   4
#define DINNER  768
#define DTRANK  24
#define HIDF    768
#define MTOK    (BB*LSEQ)             // 32768
#define DBLW    (DTRANK + 2*NSTATE)   // 56

// ---------------- scratch (static device globals; no allocation) ----------------
// feature-major (transposed) buffers: [feature][b*LSEQ + t]
__device__ float g_x  [MTOK*DIMC];        // residual, row-major [m][DIMC]
__device__ float g_xn [MTOK*DIMC];        // LN out,  row-major
__device__ float g_xzT[2*DINNER*MTOK];    // in_proj out, feature-major
__device__ float g_xiT[DINNER*MTOK];      // conv out,   feature-major
__device__ float g_dblT[DBLW*MTOK];       // xproj out,  feature-major
__device__ float g_dtT[DINNER*MTOK];      // dtproj out, feature-major
__device__ float g_y  [MTOK*DINNER];      // scan out feature-major / ff hidden row-major

// ---------------- helpers ----------------
__device__ __forceinline__ float siluf(float v) {
    return v / (1.0f + expf(-v));
}
__device__ __forceinline__ float softplusf(float v) {
    return (v >= 0.0f) ? (v + log1pf(expf(-v))) : log1pf(expf(v));
}
__device__ __forceinline__ float geluf(float v) {
    float c = 0.7978845608028654f * (v + 0.044715f * v * v * v);
    return 0.5f * v * (1.0f + tanhf(c));
}

// ---------------- elementwise: x = x + pos_emb ----------------
__global__ void add_pos_kernel(const float* __restrict__ x,
                               const float* __restrict__ pos,
                               float* __restrict__ out) {
    int idx = blockIdx.x * blockDim.x + threadIdx.x;
    if (idx >= MTOK * DIMC / 4) return;
    int m  = idx / (DIMC / 4);
    int c4 = idx % (DIMC / 4);
    int l  = m & (LSEQ - 1);
    float4 xv = ((const float4*)x)[idx];
    float4 pv = ((const float4*)pos)[l * (DIMC / 4) + c4];
    xv.x += pv.x; xv.y += pv.y; xv.z += pv.z; xv.w += pv.w;
    ((float4*)out)[idx] = xv;
}

// ---------------- layernorm over DIMC=384 (one warp per token) ----------------
__global__ void ln_kernel(const float* __restrict__ x, float* __restrict__ o,
                          const float* __restrict__ s, const float* __restrict__ bb) {
    int gwarp = (blockIdx.x * blockDim.x + threadIdx.x) >> 5;
    int lane  = threadIdx.x & 31;
    if (gwarp >= MTOK) return;
    const float* xp = x + (size_t)gwarp * DIMC;
    float4 v0 = *(const float4*)(xp + lane * 4);
    float4 v1 = *(const float4*)(xp + 128 + lane * 4);
    float4 v2 = *(const float4*)(xp + 256 + lane * 4);
    float sum = v0.x + v0.y + v0.z + v0.w
              + v1.x + v1.y + v1.z + v1.w
              + v2.x + v2.y + v2.z + v2.w;
    #pragma unroll
    for (int off = 16; off >= 1; off >>= 1) sum += __shfl_xor_sync(0xffffffffu, sum, off);
    float mean = sum * (1.0f / DIMC);
    float q = 0.0f;
    #define QACC(t) { float d_ = (t) - mean; q = fmaf(d_, d_, q); }
    QACC(v0.x) QACC(v0.y) QACC(v0.z) QACC(v0.w)
    QACC(v1.x) QACC(v1.y) QACC(v1.z) QACC(v1.w)
    QACC(v2.x) QACC(v2.y) QACC(v2.z) QACC(v2.w)
    #undef QACC
    #pragma unroll
    for (int off = 16; off >= 1; off >>= 1) q += __shfl_xor_sync(0xffffffffu, q, off);
    float rstd = rsqrtf(q * (1.0f / DIMC) + 1e-5f);

    float4 s0 = *(const float4*)(s + lane * 4);
    float4 s1 = *(const float4*)(s + 128 + lane * 4);
    float4 s2 = *(const float4*)(s + 256 + lane * 4);
    float4 b0 = *(const float4*)(bb + lane * 4);
    float4 b1 = *(const float4*)(bb + 128 + lane * 4);
    float4 b2 = *(const float4*)(bb + 256 + lane * 4);
    float* op = o + (size_t)gwarp * DIMC;
    float4 r;
    r.x = (v0.x - mean) * rstd * s0.x + b0.x;
    r.y = (v0.y - mean) * rstd * s0.y + b0.y;
    r.z = (v0.z - mean) * rstd * s0.z + b0.z;
    r.w = (v0.w - mean) * rstd * s0.w + b0.w;
    *(float4*)(op + lane * 4) = r;
    r.x = (v1.x - mean) * rstd * s1.x + b1.x;
    r.y = (v1.y - mean) * rstd * s1.y + b1.y;
    r.z = (v1.z - mean) * rstd * s1.z + b1.z;
    r.w = (v1.w - mean) * rstd * s1.w + b1.w;
    *(float4*)(op + 128 + lane * 4) = r;
    r.x = (v2.x - mean) * rstd * s2.x + b2.x;
    r.y = (v2.y - mean) * rstd * s2.y + b2.y;
    r.z = (v2.z - mean) * rstd * s2.z + b2.z;
    r.w = (v2.w - mean) * rstd * s2.w + b2.w;
    *(float4*)(op + 256 + lane * 4) = r;
}

// ============================================================================
// Proven TN SGEMM inner core (round-5 config) with layout flags:
//   AT=0: A is [M][K] row-major (lda = row stride)
//   AT=1: A is [K][M] feature-major (lda = M)
//   CT=0: C row-major [M][N] (ldc = row stride)
//   CT=1: C feature-major [N][M] (ldc = M)
// EPI: 0=store, 1=softplus(v+bias), 2=gelu(v+bias), 3=C+=v, 4=C+=v+bias
// M%128==0 and K%8==0 required. N guarded.
// ============================================================================
#define BM 128
#define BN 128
#define BKK 8

template <int AT, int CT, int EPI>
__global__ void __launch_bounds__(256)
sgemm2(const float* __restrict__ A, const float* __restrict__ W,
       float* __restrict__ C, const float* __restrict__ bias,
       int M, int N, int K, int lda, int ldw, int ldc) {
    __shared__ __align__(16) float As[BKK][BM + 4];
    __shared__ __align__(16) float Bs[BKK][BN + 4];

    int m0 = blockIdx.y * BM;
    int n0 = blockIdx.x * BN;
    int tid = threadIdx.x;
    int lrow = tid >> 1;            // 0..127
    int lcol = (tid & 1) * 4;       // 0 or 4
    int tx = tid & 15, ty = tid >> 4;
    int wk = tid >> 5;              // AT staging: k-row 0..7
    int wl = tid & 31;              // AT staging: lane

    float acc[8][8];
    #pragma unroll
    for (int i = 0; i < 8; i++)
        #pragma unroll
        for (int j = 0; j < 8; j++) acc[i][j] = 0.0f;

    // first prefetch
    float4 ra;
    if (AT) {
        ra = *(const float4*)(A + (size_t)wk * lda + m0 + wl * 4);
    } else {
        ra = *(const float4*)(A + (size_t)(m0 + lrow) * lda + lcol);
    }
    float4 rb;
    {
        int n = n0 + lrow;
        rb = (n < N) ? *(const float4*)(W + (size_t)n * ldw + lcol)
                     : make_float4(0.f, 0.f, 0.f, 0.f);
    }

    for (int k0 = 0; k0 < K; k0 += BKK) {
        if (AT) {
            *(float4*)&As[wk][wl * 4] = ra;
        } else {
            As[lcol + 0][lrow] = ra.x;
            As[lcol + 1][lrow] = ra.y;
            As[lcol + 2][lrow] = ra.z;
            As[lcol + 3][lrow] = ra.w;
        }
        Bs[lcol + 0][lrow] = rb.x;
        Bs[lcol + 1][lrow] = rb.y;
        Bs[lcol + 2][lrow] = rb.z;
        Bs[lcol + 3][lrow] = rb.w;
        __syncthreads();

        if (k0 + BKK < K) {
            if (AT) {
                ra = *(const float4*)(A + (size_t)(k0 + BKK + wk) * lda + m0 + wl * 4);
            } else {
                ra = *(const float4*)(A + (size_t)(m0 + lrow) * lda + (k0 + BKK) + lcol);
            }
            int n = n0 + lrow;
            rb = (n < N) ? *(const float4*)(W + (size_t)n * ldw + (k0 + BKK) + lcol)
                         : make_float4(0.f, 0.f, 0.f, 0.f);
        }

        #pragma unroll
        for (int k = 0; k < BKK; k++) {
            float4 a0 = *(const float4*)&As[k][ty * 4];
            float4 a1 = *(const float4*)&As[k][ty * 4 + 64];
            float4 b0 = *(const float4*)&Bs[k][tx * 4];
            float4 b1 = *(const float4*)&Bs[k][tx * 4 + 64];
            float av[8] = {a0.x, a0.y, a0.z, a0.w, a1.x, a1.y, a1.z, a1.w};
            float bv[8] = {b0.x, b0.y, b0.z, b0.w, b1.x, b1.y, b1.z, b1.w};
            #pragma unroll
            for (int ii = 0; ii < 8; ii++)
                #pragma unroll
                for (int jj = 0; jj < 8; jj++)
                    acc[ii][jj] = fmaf(av[ii], bv[jj], acc[ii][jj]);
        }
        __syncthreads();
    }

    if (CT) {
        // transposed store: one column -> contiguous row of C[N][M]
        #pragma unroll
        for (int jj = 0; jj < 8; jj++) {
            int c = n0 + tx * 4 + ((jj < 4) ? jj : 60 + jj);
            if (c >= N) continue;
            float bc = (EPI == 1 || EPI == 2) ? bias[c] : 0.0f;
            float v[8];
            #pragma unroll
            for (int ii = 0; ii < 8; ii++) {
                float t = acc[ii][jj];
                if (EPI == 1)      t = softplusf(t + bc);
                else if (EPI == 2) t = geluf(t + bc);
                v[ii] = t;
            }
            float* crow = C + (size_t)c * ldc + m0 + ty * 4;
            *(float4*)(crow)      = make_float4(v[0], v[1], v[2], v[3]);
            *(float4*)(crow + 64) = make_float4(v[4], v[5], v[6], v[7]);
        }
    } else {
        #pragma unroll
        for (int ii = 0; ii < 8; ii++) {
            int r = m0 + ty * 4 + ((ii < 4) ? ii : 60 + ii);
            float* crow = C + (size_t)r * ldc;
            #pragma unroll
            for (int jj = 0; jj < 8; jj++) {
                int c = n0 + tx * 4 + ((jj < 4) ? jj : 60 + jj);
                if (c >= N) continue;
                float v = acc[ii][jj];
                if (EPI == 0)      crow[c] = v;
                else if (EPI == 1) crow[c] = softplusf(v + bias[c]);
                else if (EPI == 2) crow[c] = geluf(v + bias[c]);
                else if (EPI == 3) crow[c] += v;
                else               crow[c] += v + bias[c];
            }
        }
    }
}

// ============================================================================
// xproj GEMM: dblT[56][M] = (xiT[768][M])^T-logical @ W[56][768]^T
// BN=64 tile, A feature-major staging, transposed store. Grid (1, M/128).
// ============================================================================
__global__ void __launch_bounds__(256)
xgemm64T(const float* __restrict__ A, const float* __restrict__ W,
         float* __restrict__ C, int M, int K) {
    __shared__ __align__(16) float As[BKK][BM + 4];
    __shared__ __align__(16) float Bs[BKK][64 + 4];

    int m0 = blockIdx.y * BM;
    int tid = threadIdx.x;
    int wk = tid >> 5;              // 0..7
    int wl = tid & 31;
    int brow = (tid & 127) >> 1;    // 0..63
    int bcol = (tid & 1) * 4;
    bool bload  = (tid < 128);
    bool bvalid = bload && (brow < DBLW);
    int tx = tid & 15, ty = tid >> 4;

    float acc[8][4];
    #pragma unroll
    for (int i = 0; i < 8; i++)
        #pragma unroll
        for (int j = 0; j < 4; j++) acc[i][j] = 0.0f;

    const float* Wp = W + (size_t)(bvalid ? brow : 0) * K;

    float4 ra = *(const float4*)(A + (size_t)wk * M + m0 + wl * 4);
    float4 rb = bvalid ? *(const float4*)(Wp + bcol)
                       : make_float4(0.f, 0.f, 0.f, 0.f);

    for (int k0 = 0; k0 < K; k0 += BKK) {
        *(float4*)&As[wk][wl * 4] = ra;
        if (bload) {
            Bs[bcol + 0][brow] = rb.x;
            Bs[bcol + 1][brow] = rb.y;
            Bs[bcol + 2][brow] = rb.z;
            Bs[bcol + 3][brow] = rb.w;
        }
        __syncthreads();

        if (k0 + BKK < K) {
            ra = *(const float4*)(A + (size_t)(k0 + BKK + wk) * M + m0 + wl * 4);
            rb = bvalid ? *(const float4*)(Wp + (k0 + BKK) + bcol)
                        : make_float4(0.f, 0.f, 0.f, 0.f);
        }

        #pragma unroll
        for (int k = 0; k < BKK; k++) {
            float4 a0 = *(const float4*)&As[k][ty * 4];
            float4 a1 = *(const float4*)&As[k][ty * 4 + 64];
            float4 b0 = *(const float4*)&Bs[k][tx * 4];
            float av[8] = {a0.x, a0.y, a0.z, a0.w, a1.x, a1.y, a1.z, a1.w};
            float bv[4] = {b0.x, b0.y, b0.z, b0.w};
            #pragma unroll
            for (int ii = 0; ii < 8; ii++)
                #pragma unroll
                for (int jj = 0; jj < 4; jj++)
                    acc[ii][jj] = fmaf(av[ii], bv[jj], acc[ii][jj]);
        }
        __syncthreads();
    }

    #pragma unroll
    for (int jj = 0; jj < 4; jj++) {
        int c = tx * 4 + jj;
        if (c >= DBLW) continue;
        float* crow = C + (size_t)c * M + m0 + ty * 4;
        *(float4*)(crow)      = make_float4(acc[0][jj], acc[1][jj], acc[2][jj], acc[3][jj]);
        *(float4*)(crow + 64) = make_float4(acc[4][jj], acc[5][jj], acc[6][jj], acc[7][jj]);
    }
}

// ---------------- causal conv (DCONV=4) + silu, feature-major ----------------
// thread = one channel x 4 consecutive tokens; fully contiguous loads/stores
__global__ void conv_silu_T(const float* __restrict__ xzT, float* __restrict__ xiT,
                            const float* __restrict__ w, const float* __restrict__ cb) {
    int idx = blockIdx.x * blockDim.x + threadIdx.x;   // over DINNER*BB*(LSEQ/4)
    if (idx >= DINNER * BB * (LSEQ / 4)) return;
    int tq = idx & (LSEQ / 4 - 1);
    int bd = idx >> 10;                 // LSEQ/4 = 1024
    int b  = bd & (BB - 1);
    int d  = bd >> 3;
    int t0 = tq * 4;

    const float* row = xzT + (size_t)d * MTOK + (size_t)b * LSEQ;
    float4 cur  = *(const float4*)(row + t0);
    float4 prev = (t0 == 0) ? make_float4(0.f, 0.f, 0.f, 0.f)
                            : *(const float4*)(row + t0 - 4);

    float w0 = w[d * NCONV + 0], w1 = w[d * NCONV + 1];
    float w2 = w[d * NCONV + 2], w3 = w[d * NCONV + 3];
    float cbd = cb[d];

    // y[t] = cb + w0*x[t-3] + w1*x[t-2] + w2*x[t-1] + w3*x[t]
    float4 o;
    o.x = cbd; o.x = fmaf(w0, prev.y, o.x); o.x = fmaf(w1, prev.z, o.x);
    o.x = fmaf(w2, prev.w, o.x); o.x = fmaf(w3, cur.x, o.x);
    o.y = cbd; o.y = fmaf(w0, prev.z, o.y); o.y = fmaf(w1, prev.w, o.y);
    o.y = fmaf(w2, cur.x, o.y);  o.y = fmaf(w3, cur.y, o.y);
    o.z = cbd; o.z = fmaf(w0, prev.w, o.z); o.z = fmaf(w1, cur.x, o.z);
    o.z = fmaf(w2, cur.y, o.z);  o.z = fmaf(w3, cur.z, o.z);
    o.w = cbd; o.w = fmaf(w0, cur.x, o.w);  o.w = fmaf(w1, cur.y, o.w);
    o.w = fmaf(w2, cur.z, o.w);  o.w = fmaf(w3, cur.w, o.w);

    o.x = siluf(o.x); o.y = siluf(o.y); o.z = siluf(o.z); o.w = siluf(o.w);
    *(float4*)(xiT + (size_t)d * MTOK + (size_t)b * LSEQ + t0) = o;
}

// ---------------- selective scan, feature-major streams, gate fused ----------
__global__ void __launch_bounds__(256)
scan_T(const float* __restrict__ xiT, const float* __restrict__ dtT,
       const float* __restrict__ dblT, const float* __restrict__ A_log,
       const float* __restrict__ Dp, const float* __restrict__ xzT,
       float* __restrict__ yT) {
    int b    = blockIdx.x;
    int dblk = blockIdx.y;
    int tid  = threadIdx.x;
    int dl   = tid >> 4;
    int s    = tid & 15;
    int d    = dblk * 16 + dl;

    float aL2 = -expf(A_log[d * NSTATE + s]) * 1.4426950408889634f;
    float Dd  = Dp[d];
    float h = 0.0f;

    const size_t bt = (size_t)b * LSEQ;
    const float* dt_row = dtT  + (size_t)d * MTOK + bt;
    const float* u_row  = xiT  + (size_t)d * MTOK + bt;
    const float* B_row  = dblT + (size_t)(DTRANK + s) * MTOK + bt;
    const float* C_row  = dblT + (size_t)(DTRANK + NSTATE + s) * MTOK + bt;
    const float* z_row  = xzT  + (size_t)(DINNER + d) * MTOK + bt;
    float*       y_row  = yT   + (size_t)d * MTOK + bt;

    for (int t0 = 0; t0 < LSEQ; t0 += 4) {
        float4 dt4 = *(const float4*)(dt_row + t0);   // broadcast across 16 lanes
        float4 u4  = *(const float4*)(u_row + t0);    // broadcast
        float4 B4  = *(const float4*)(B_row + t0);    // per-lane stream
        float4 C4  = *(const float4*)(C_row + t0);
        float4 z4 = make_float4(0.f, 0.f, 0.f, 0.f);
        if (s == 0) z4 = *(const float4*)(z_row + t0);

        float dta[4] = {dt4.x, dt4.y, dt4.z, dt4.w};
        float ua[4]  = {u4.x, u4.y, u4.z, u4.w};
        float Ba[4]  = {B4.x, B4.y, B4.z, B4.w};
        float Ca[4]  = {C4.x, C4.y, C4.z, C4.w};
        float za[4]  = {z4.x, z4.y, z4.z, z4.w};
        float ya[4];

        #pragma unroll
        for (int j = 0; j < 4; j++) {
            float dtv = dta[j];
            float uv  = ua[j];
            float dA  = exp2f(dtv * aL2);
            h = fmaf(h, dA, (dtv * uv) * Ba[j]);
            float p = h * Ca[j];
            p += __shfl_xor_sync(0xffffffffu, p, 8);
            p += __shfl_xor_sync(0xffffffffu, p, 4);
            p += __shfl_xor_sync(0xffffffffu, p, 2);
            p += __shfl_xor_sync(0xffffffffu, p, 1);
            ya[j] = fmaf(uv, Dd, p) * siluf(za[j]);
        }
        if (s == 0) {
            *(float4*)(y_row + t0) = make_float4(ya[0], ya[1], ya[2], ya[3]);
        }
    }
}

// ---------------- host launcher ----------------
static inline int cdiv(int a, int b) { return (a + b - 1) / b; }

extern "C" void kernel_launch(void* const* d_in, const int* in_sizes, int n_in,
                              void* d_out, int out_size) {
    const float* x_in     = (const float*)d_in[0];
    const float* pos      = (const float*)d_in[1];
    const float* ln1_s    = (const float*)d_in[2];
    const float* ln1_b    = (const float*)d_in[3];
    const float* in_w     = (const float*)d_in[4];
    const float* conv_w   = (const float*)d_in[5];
    const float* conv_b   = (const float*)d_in[6];
    const float* xproj_w  = (const float*)d_in[7];
    const float* dtproj_w = (const float*)d_in[8];
    const float* dtproj_b = (const float*)d_in[9];
    const float* A_log    = (const float*)d_in[10];
    const float* Dp       = (const float*)d_in[11];
    const float* out_w    = (const float*)d_in[12];
    const float* ff_ln_s  = (const float*)d_in[13];
    const float* ff_ln_b  = (const float*)d_in[14];
    const float* ff_w1    = (const float*)d_in[15];
    const float* ff_b1    = (const float*)d_in[16];
    const float* ff_w2    = (const float*)d_in[17];
    const float* ff_b2    = (const float*)d_in[18];
    const float* lno_s    = (const float*)d_in[19];
    const float* lno_b    = (const float*)d_in[20];

    float *bx, *bxn, *bxzT, *bxiT, *bdblT, *bdtT, *by;
    cudaGetSymbolAddress((void**)&bx,    g_x);
    cudaGetSymbolAddress((void**)&bxn,   g_xn);
    cudaGetSymbolAddress((void**)&bxzT,  g_xzT);
    cudaGetSymbolAddress((void**)&bxiT,  g_xiT);
    cudaGetSymbolAddress((void**)&bdblT, g_dblT);
    cudaGetSymbolAddress((void**)&bdtT,  g_dtT);
    cudaGetSymbolAddress((void**)&by,    g_y);

    const int EW_BLK = 256;
    int ew_dim  = cdiv(MTOK * DIMC / 4, EW_BLK);
    int ew_conv = cdiv(DINNER * BB * (LSEQ / 4), EW_BLK);

    // x = x + pos_emb
    add_pos_kernel<<<ew_dim, EW_BLK>>>(x_in, pos, bx);

    for (int i = 0; i < NDEPTH; i++) {
        // ---- mamba block ----
        ln_kernel<<<MTOK / 8, 256>>>(bx, bxn, ln1_s + (size_t)i * DIMC, ln1_b + (size_t)i * DIMC);

        // xzT[1536][M] = (xn @ in_w^T)^T
        sgemm2<0, 1, 0><<<dim3((2 * DINNER) / BN, MTOK / BM), 256>>>(
            bxn, in_w + (size_t)i * 2 * DINNER * DIMC, bxzT, nullptr,
            MTOK, 2 * DINNER, DIMC, DIMC, DIMC, MTOK);

        // xiT = silu(conv1d(xzT rows 0..767))
        conv_silu_T<<<ew_conv, EW_BLK>>>(
            bxzT, bxiT, conv_w + (size_t)i * DINNER * NCONV, conv_b + (size_t)i * DINNER);

        // dblT[56][M] = (xi @ xproj_w^T)^T
        xgemm64T<<<dim3(1, MTOK / BM), 256>>>(
            bxiT, xproj_w + (size_t)i * DBLW * DINNER, bdblT, MTOK, DINNER);

        // dtT[768][M] = softplus(dbl[:, :24] @ dtproj_w^T + b)^T   (A = dblT rows 0..23)
        sgemm2<1, 1, 1><<<dim3(DINNER / BN, MTOK / BM), 256>>>(
            bdblT, dtproj_w + (size_t)i * DINNER * DTRANK, bdtT,
            dtproj_b + (size_t)i * DINNER,
            MTOK, DINNER, DTRANK, MTOK, DTRANK, MTOK);

        // selective scan + gate -> yT[768][M]
        scan_T<<<dim3(BB, DINNER / 16), 256>>>(
            bxiT, bdtT, bdblT, A_log + (size_t)i * DINNER * NSTATE,
            Dp + (size_t)i * DINNER, bxzT, by);

        // x += y @ out_w^T   (A = yT feature-major)
        sgemm2<1, 0, 3><<<dim3(DIMC / BN, MTOK / BM), 256>>>(
            by, out_w + (size_t)i * DIMC * DINNER, bx, nullptr,
            MTOK, DIMC, DINNER, MTOK, DINNER, DIMC);

        // ---- feed-forward block ----
        ln_kernel<<<MTOK / 8, 256>>>(bx, bxn, ff_ln_s + (size_t)i * DIMC, ff_ln_b + (size_t)i * DIMC);

        // h = gelu(xn @ ff_w1^T + b1)   (row-major h in g_y)
        sgemm2<0, 0, 2><<<dim3(HIDF / BN, MTOK / BM), 256>>>(
            bxn, ff_w1 + (size_t)i * HIDF * DIMC, by, ff_b1 + (size_t)i * HIDF,
            MTOK, HIDF, DIMC, DIMC, DIMC, HIDF);

        // x += h @ ff_w2^T + b2
        sgemm2<0, 0, 4><<<dim3(DIMC / BN, MTOK / BM), 256>>>(
            by, ff_w2 + (size_t)i * DIMC * HIDF, bx, ff_b2 + (size_t)i * DIMC,
            MTOK, DIMC, HIDF, HIDF, HIDF, DIMC);
    }

    // final layernorm -> d_out
    ln_kernel<<<MTOK / 8, 256>>>(bx, (float*)d_out, lno_s, lno_b);
}